// round 7
// baseline (speedup 1.0000x reference)
#include <cuda_runtime.h>

#define HH 4096
#define WW 4096
#define CC 3
#define R  8
#define OX 112          // output tile width
#define VX 128          // OX + 2R  (vsum columns)
#define OY 32           // output tile height per pipeline stage
#define KTILES 4        // y-tiles processed per CTA (software pipeline)
#define QROWS 16        // output rows per thread-group
#define NROWS 32        // QROWS + 2R staged input rows
#define NT 256
#define SEGW 14         // OX / 8
#define V4STRIDE 129    // float4 per VS row (odd -> conflict-free)
#define ITSTRIDE 113    // odd -> conflict-free across rows
#define EPSF 1e-4f

#define VS_FLOATS (OY * V4STRIDE * 4)
#define IT_FLOATS (OY * ITSTRIDE)
#define SMEM_BYTES ((VS_FLOATS + IT_FLOATS) * 4)

__device__ __forceinline__ void load_tile(
    const float* __restrict__ Ib, const float* __restrict__ Pb,
    int x0, int col, int yfirst, bool inter,
    float ivr[NROWS], float pvr[NROWS])
{
    if (inter) {
        const float* pI = Ib + (size_t)yfirst * WW + (x0 + col - R);
        const float* pP = Pb + (size_t)yfirst * WW + (x0 + col - R);
        #pragma unroll
        for (int k = 0; k < NROWS; ++k) {
            ivr[k] = __ldg(pI + (size_t)k * WW);
            pvr[k] = __ldg(pP + (size_t)k * WW);
        }
    } else {
        const int xg = x0 + col - R;
        int xgc = xg; if (xgc < 0) xgc = 0; if (xgc > WW - 1) xgc = WW - 1;
        const float xmask = (xg >= 0 && xg < WW) ? 1.f : 0.f;
        #pragma unroll
        for (int k = 0; k < NROWS; ++k) {
            int y = yfirst + k;
            int yc = y; if (yc < 0) yc = 0; if (yc > HH - 1) yc = HH - 1;
            size_t off = (size_t)yc * WW + xgc;
            ivr[k] = __ldg(Ib + off);
            pvr[k] = __ldg(Pb + off);
        }
        #pragma unroll
        for (int k = 0; k < NROWS; ++k) {
            int y = yfirst + k;
            float m = (y >= 0 && y < HH) ? xmask : 0.f;
            ivr[k] *= m;
            pvr[k] *= m;
        }
    }
}

__global__ __launch_bounds__(NT, 2)
void gf_kernel(const float* __restrict__ I, const float* __restrict__ P,
               float* __restrict__ Q)
{
    extern __shared__ float sm[];
    float* VSf = sm;                 // [OY][V4STRIDE] of float4 {si,sp,spi,sii}
    float* IT  = sm + VS_FLOATS;     // [OY][ITSTRIDE] (i tile, then q tile)
    float4* VS = (float4*)VSf;

    const int x0    = blockIdx.x * OX;
    const int ybase = blockIdx.y * (KTILES * OY);
    const long base = (long)blockIdx.z * HH * WW;
    const float* Ib = I + base;
    const float* Pb = P + base;
    const int tid = threadIdx.x;

    const bool xInt = (x0 >= R) && (x0 + OX + R <= WW);

    const int col   = tid & (VX - 1);   // 0..127  (phase-1 mapping)
    const int group = tid >> 7;         // 0..1

    float ivr[NROWS], pvr[NROWS];

    // ---- prologue: load staging registers for tile 0 --------------------
    {
        const int y0 = ybase;
        const bool inter = xInt && (y0 >= R) && (y0 + OY + R <= HH);
        load_tile(Ib, Pb, x0, col, y0 + group * QROWS - R, inter, ivr, pvr);
    }

    #pragma unroll 1
    for (int t = 0; t < KTILES; ++t) {
        const int y0 = ybase + t * OY;
        const bool interior = xInt && (y0 >= R) && (y0 + OY + R <= HH);

        // ---------- Phase 1: vertical box sums from staged registers -----
        {
            // stash central i values for the epilogue
            if (col >= R && col < R + OX) {
                #pragma unroll
                for (int k = 0; k < QROWS; ++k)
                    IT[(group * QROWS + k) * ITSTRIDE + (col - R)] = ivr[k + R];
            }

            float si = 0.f, sp = 0.f, spi = 0.f, sii = 0.f;
            #pragma unroll
            for (int k = 0; k <= 2 * R; ++k) {
                si  += ivr[k];
                sp  += pvr[k];
                spi += pvr[k] * ivr[k];
                sii += ivr[k] * ivr[k];
            }
            float4* vp = VS + (group * QROWS) * V4STRIDE + col;
            *vp = make_float4(si, sp, spi, sii);

            #pragma unroll
            for (int rr = 1; rr < QROWS; ++rr) {
                float ia = ivr[rr + 2 * R], pa = pvr[rr + 2 * R];
                float ib = ivr[rr - 1],     pb = pvr[rr - 1];
                si  += ia - ib;
                sp  += pa - pb;
                spi += pa * ia - pb * ib;
                sii += ia * ia - ib * ib;
                vp += V4STRIDE;
                *vp = make_float4(si, sp, spi, sii);
            }
        }

        // ---------- Prefetch next tile's inputs (overlaps phases 2/3) ----
        if (t + 1 < KTILES) {
            const int y1 = y0 + OY;
            const bool inter1 = xInt && (y1 >= R) && (y1 + OY + R <= HH);
            load_tile(Ib, Pb, x0, col, y1 + group * QROWS - R, inter1, ivr, pvr);
        }
        __syncthreads();

        // ---------- Phase 2: horizontal sums + guided-filter math --------
        {
            const int row = tid & (OY - 1);   // 0..31
            const int seg = tid >> 5;         // 0..7
            const int xs = seg * SEGW;
            const float4* vrow = VS + row * V4STRIDE;
            float* itrow = IT + row * ITSTRIDE;

            float h0 = 0.f, h1 = 0.f, h2 = 0.f, h3 = 0.f;
            #pragma unroll
            for (int d = 0; d < 2 * R + 1; ++d) {
                float4 tt = vrow[xs + d];
                h0 += tt.x; h1 += tt.y; h2 += tt.z; h3 += tt.w;
            }

            if (interior) {
                const float invN = 1.0f / ((2 * R + 1) * (2 * R + 1));
                #pragma unroll
                for (int j = 0; j < SEGW; ++j) {
                    int xo = xs + j;
                    float mi  = h0 * invN;
                    float mp  = h1 * invN;
                    float mpi = h2 * invN;
                    float mii = h3 * invN;
                    float cov_ip = mpi - mp * mi;
                    float cov_ii = mii - mi * mi;
                    float a = __fdividef(cov_ip, cov_ii + EPSF);
                    float b = mp - a * mi;
                    float iv = itrow[xo];
                    float q = fminf(fmaxf(a * iv + b, 0.f), 1.f);
                    itrow[xo] = q;
                    if (j < SEGW - 1) {
                        float4 ta = vrow[xo + 2 * R + 1];
                        float4 tb = vrow[xo];
                        h0 += ta.x - tb.x;
                        h1 += ta.y - tb.y;
                        h2 += ta.z - tb.z;
                        h3 += ta.w - tb.w;
                    }
                }
            } else {
                const int yg = y0 + row;
                int yl = yg - R; if (yl < 0) yl = 0;
                int yh = yg + R; if (yh > HH - 1) yh = HH - 1;
                const float ny = (float)(yh - yl + 1);
                #pragma unroll
                for (int j = 0; j < SEGW; ++j) {
                    int xo = xs + j;
                    int xg = x0 + xo;
                    if (xg < WW) {
                        int xl = xg - R; if (xl < 0) xl = 0;
                        int xh = xg + R; if (xh > WW - 1) xh = WW - 1;
                        float nx = (float)(xh - xl + 1);
                        float invN = __fdividef(1.0f, ny * nx);
                        float mi  = h0 * invN;
                        float mp  = h1 * invN;
                        float mpi = h2 * invN;
                        float mii = h3 * invN;
                        float cov_ip = mpi - mp * mi;
                        float cov_ii = mii - mi * mi;
                        float a = __fdividef(cov_ip, cov_ii + EPSF);
                        float b = mp - a * mi;
                        float iv = itrow[xo];
                        float q = fminf(fmaxf(a * iv + b, 0.f), 1.f);
                        itrow[xo] = q;
                    }
                    if (j < SEGW - 1) {
                        float4 ta = vrow[xo + 2 * R + 1];
                        float4 tb = vrow[xo];
                        h0 += ta.x - tb.x;
                        h1 += ta.y - tb.y;
                        h2 += ta.z - tb.z;
                        h3 += ta.w - tb.w;
                    }
                }
            }
        }
        __syncthreads();

        // ---------- Phase 3: coalesced store of q ------------------------
        {
            float* Qb = Q + base + (size_t)y0 * WW + x0;
            int row = tid / OX;
            int xo  = tid - row * OX;
            if (x0 + OX <= WW) {
                #pragma unroll
                for (int it = 0; it < (OY * OX) / NT; ++it) {   // 14 exact
                    Qb[(size_t)row * WW + xo] = IT[row * ITSTRIDE + xo];
                    xo += NT - 2 * OX;     // 256 = 2*112 + 32
                    row += 2;
                    if (xo >= OX) { xo -= OX; row += 1; }
                }
            } else {
                #pragma unroll
                for (int it = 0; it < (OY * OX) / NT; ++it) {
                    if (x0 + xo < WW)
                        Qb[(size_t)row * WW + xo] = IT[row * ITSTRIDE + xo];
                    xo += NT - 2 * OX;
                    row += 2;
                    if (xo >= OX) { xo -= OX; row += 1; }
                }
            }
        }
        __syncthreads();   // IT/VS reused by next tile's phase 1
    }
}

extern "C" void kernel_launch(void* const* d_in, const int* in_sizes, int n_in,
                              void* d_out, int out_size)
{
    const float* I = (const float*)d_in[0];
    const float* P = (const float*)d_in[1];
    float* Q = (float*)d_out;

    cudaFuncSetAttribute(gf_kernel,
                         cudaFuncAttributeMaxDynamicSharedMemorySize,
                         SMEM_BYTES);

    dim3 grid((WW + OX - 1) / OX, HH / (KTILES * OY), CC);
    gf_kernel<<<grid, NT, SMEM_BYTES>>>(I, P, Q);
}